// round 16
// baseline (speedup 1.0000x reference)
#include <cuda_runtime.h>
#include <cuda_bf16.h>

#define NSAMPLE 32
#define NPTS 4096
#define MAXB 8
#define BLOCK_THREADS 64
#define WARPS_PER_BLOCK (BLOCK_THREADS / 32)
#define SCR_SLOTS 320            // max slot overshoot: 31 + 256 = 287

// Layout (R14, unchanged): per 64-point chunk-pair cp, 64 contiguous float4s:
//   [cp*64 + l]      = (x_n0, x_n1, y_n0, y_n1)   n0 = cp*64+l, n1 = n0+32
//   [cp*64 + 32 + l] = (z_n0, z_n1, w_n0, w_n1)
// Lanes 16B-contiguous -> 4 L1 wavefronts per LDG.128; operand pairs land in
// adjacent registers so pk2 folds away. +256 pad for depth-8 prefetch overrun.
__device__ float4 g_pk[MAXB * NPTS + 256];

// ---- f32x2 helpers (sm_103a); arithmetic FROZEN (rel_err 7.915904e-4).
__device__ __forceinline__ unsigned long long pk2(float lo, float hi) {
    unsigned long long r;
    asm("mov.b64 %0, {%1, %2};" : "=l"(r) : "f"(lo), "f"(hi));
    return r;
}
__device__ __forceinline__ void upk2(unsigned long long v, float& lo, float& hi) {
    asm("mov.b64 {%0, %1}, %2;" : "=f"(lo), "=f"(hi) : "l"(v));
}
__device__ __forceinline__ unsigned long long mul2(unsigned long long a,
                                                   unsigned long long b) {
    unsigned long long r;
    asm("mul.rn.f32x2 %0, %1, %2;" : "=l"(r) : "l"(a), "l"(b));
    return r;
}
__device__ __forceinline__ unsigned long long add2(unsigned long long a,
                                                   unsigned long long b) {
    unsigned long long r;
    asm("add.rn.f32x2 %0, %1, %2;" : "=l"(r) : "l"(a), "l"(b));
    return r;
}

// Pre-pass (R14 unchanged). |p|^2 expression FROZEN.
__global__ void pack_kernel(const float* __restrict__ xyz, int total_pairs) {
    const int j = blockIdx.x * blockDim.x + threadIdx.x;
    if (j >= total_pairs) return;
    const int b = j / (NPTS / 2);
    const int s = j - b * (NPTS / 2);
    const int cp = s >> 5;
    const int l = s & 31;
    const int n0 = b * NPTS + cp * 64 + l;
    const int n1 = n0 + 32;

    const float x0 = xyz[n0 * 3 + 0], y0 = xyz[n0 * 3 + 1], z0 = xyz[n0 * 3 + 2];
    const float x1 = xyz[n1 * 3 + 0], y1 = xyz[n1 * 3 + 1], z1 = xyz[n1 * 3 + 2];
    const float w0 = __fadd_rn(__fadd_rn(__fmul_rn(x0, x0), __fmul_rn(y0, y0)),
                               __fmul_rn(z0, z0));
    const float w1 = __fadd_rn(__fadd_rn(__fmul_rn(x1, x1), __fmul_rn(y1, y1)),
                               __fmul_rn(z1, z1));
    const int base = (b * (NPTS / 64) + cp) * 64;
    g_pk[base + l]      = make_float4(x0, x1, y0, y1);
    g_pk[base + 32 + l] = make_float4(z0, z1, w0, w1);
}

// Process one 64-point chunk-pair: frozen f32x2 distance math + ballot-ordered
// emission into the warp's smem scratch. Returns updated count.
__device__ __forceinline__ int do_pair(float4 a, float4 b,
                                       unsigned long long qxp, unsigned long long qyp,
                                       unsigned long long qzp, unsigned long long qwp,
                                       unsigned long long M2, float r2,
                                       unsigned mlt, float* scr_row,
                                       int count, float fA, float fB) {
    const unsigned long long dot =
        add2(add2(mul2(qxp, pk2(a.x, a.y)),
                  mul2(qyp, pk2(a.z, a.w))),
             mul2(qzp, pk2(b.x, b.y)));
    const unsigned long long d2 =
        add2(add2(qwp, pk2(b.z, b.w)), mul2(dot, M2));
    float dlo, dhi;
    upk2(d2, dlo, dhi);

    const bool h0 = dlo < r2;
    const bool h1 = dhi < r2;
    const unsigned bal0 = __ballot_sync(0xffffffffu, h0);
    const unsigned bal1 = __ballot_sync(0xffffffffu, h1);

    if (h0) scr_row[count + __popc(bal0 & mlt)] = fA;
    count += __popc(bal0);
    if (h1) scr_row[count + __popc(bal1 & mlt)] = fB;
    return count + __popc(bal1);
}

// One warp per query, 256 points/iter (8 chunks, depth-8 prefetch): R14's
// skeleton with the body unrolled 2x so loop control / break / pointer costs
// amortize over twice the points and 8 independent LDG.128s overlap the
// ballot/count chain. All fp ops bit-identical to rounds 10/12/14.
__global__ void ball_query_kernel(const float* __restrict__ xyz,
                                  float* __restrict__ out) {
    __shared__ float scr[WARPS_PER_BLOCK][SCR_SLOTS];

    const int lane = threadIdx.x & 31;
    const int w = threadIdx.x >> 5;
    const int gw = blockIdx.x * WARPS_PER_BLOCK + w;
    const int b = gw >> 12;          // / NPTS

    const float4* __restrict__ p = g_pk + (size_t)b * NPTS;

    const float qx = xyz[gw * 3 + 0];
    const float qy = xyz[gw * 3 + 1];
    const float qz = xyz[gw * 3 + 2];
    const float qw = __fadd_rn(__fadd_rn(__fmul_rn(qx, qx), __fmul_rn(qy, qy)),
                               __fmul_rn(qz, qz));
    const unsigned long long qxp = pk2(qx, qx);
    const unsigned long long qyp = pk2(qy, qy);
    const unsigned long long qzp = pk2(qz, qz);
    const unsigned long long qwp = pk2(qw, qw);
    const unsigned long long M2  = pk2(-2.0f, -2.0f);

    const unsigned mlt = (1u << lane) - 1u;
    const float r2 = 0.04f;          // f32 promotion of 0.2*0.2
    int count = 0;

    // Depth-8 prefetch (4 chunk-pairs = 256 points).
    float4 s0 = p[lane],        s1 = p[32 + lane];
    float4 s2 = p[64 + lane],   s3 = p[96 + lane];
    float4 s4 = p[128 + lane],  s5 = p[160 + lane];
    float4 s6 = p[192 + lane],  s7 = p[224 + lane];
    p += 256;

    float f0 = (float)lane;          // emission values, +256.0f per iter
    float f1 = (float)(lane + 32);
    float f2 = (float)(lane + 64);
    float f3 = (float)(lane + 96);
    float f4 = (float)(lane + 128);
    float f5 = (float)(lane + 160);
    float f6 = (float)(lane + 192);
    float f7 = (float)(lane + 224);

    for (int it = 0; it < NPTS / 256; ++it) {
        const float4 a0 = s0, b0 = s1, a1 = s2, b1 = s3;
        const float4 a2 = s4, b2 = s5, a3 = s6, b3 = s7;
        s0 = p[lane];        s1 = p[32 + lane];   // final-iter overrun -> pad
        s2 = p[64 + lane];   s3 = p[96 + lane];
        s4 = p[128 + lane];  s5 = p[160 + lane];
        s6 = p[192 + lane];  s7 = p[224 + lane];
        p += 256;

        count = do_pair(a0, b0, qxp, qyp, qzp, qwp, M2, r2, mlt, scr[w], count, f0, f1);
        count = do_pair(a1, b1, qxp, qyp, qzp, qwp, M2, r2, mlt, scr[w], count, f2, f3);
        count = do_pair(a2, b2, qxp, qyp, qzp, qwp, M2, r2, mlt, scr[w], count, f4, f5);
        count = do_pair(a3, b3, qxp, qyp, qzp, qwp, M2, r2, mlt, scr[w], count, f6, f7);

        f0 += 256.0f; f1 += 256.0f; f2 += 256.0f; f3 += 256.0f;
        f4 += 256.0f; f5 += 256.0f; f6 += 256.0f; f7 += 256.0f;

        if (count >= NSAMPLE) break;  // count is warp-uniform
    }

    __syncwarp();                     // order scratch stores within the warp
    const int sel = (lane < count) ? lane : 0;  // scr[0] == smallest hit
    out[(size_t)gw * NSAMPLE + lane] = scr[w][sel];
}

extern "C" void kernel_launch(void* const* d_in, const int* in_sizes, int n_in,
                              void* d_out, int out_size) {
    const float* xyz = (const float*)d_in[0];  // 'xyz' (B, N, 3) float32
    // d_in[1] ('xyz_new') is unused by the reference (it queries xyz vs xyz).
    const int B = in_sizes[0] / (NPTS * 3);    // 8
    float* out = (float*)d_out;

    const int total_pairs = B * (NPTS / 2);    // 16384
    pack_kernel<<<(total_pairs + 255) / 256, 256>>>(xyz, total_pairs);

    const int blocks = (B * NPTS) / WARPS_PER_BLOCK;  // 16384
    ball_query_kernel<<<blocks, BLOCK_THREADS>>>(xyz, out);
}

// round 17
// speedup vs baseline: 1.2254x; 1.2254x over previous
#include <cuda_runtime.h>
#include <cuda_bf16.h>

#define NSAMPLE 32
#define NPTS 4096
#define MAXB 8
#define BLOCK_THREADS 64
#define WARPS_PER_BLOCK (BLOCK_THREADS / 32)
#define SCR_SLOTS 192            // max slot overshoot: 31 + 128 = 159
#define TOTALQ (MAXB * NPTS)

// Layout (R14, unchanged): per 64-point chunk-pair cp, 64 contiguous float4s:
//   [cp*64 + l]      = (x_n0, x_n1, y_n0, y_n1)   n0 = cp*64+l, n1 = n0+32
//   [cp*64 + 32 + l] = (z_n0, z_n1, w_n0, w_n1)
__device__ float4 g_pk[MAXB * NPTS + 128];
__device__ int g_perm[TOTALQ];       // LPT query order: heavy first
__device__ unsigned g_cnt[2] = {0, 0};  // front / back cursors

// ---- f32x2 helpers (sm_103a); arithmetic FROZEN (rel_err 7.915904e-4).
__device__ __forceinline__ unsigned long long pk2(float lo, float hi) {
    unsigned long long r;
    asm("mov.b64 %0, {%1, %2};" : "=l"(r) : "f"(lo), "f"(hi));
    return r;
}
__device__ __forceinline__ void upk2(unsigned long long v, float& lo, float& hi) {
    asm("mov.b64 {%0, %1}, %2;" : "=f"(lo), "=f"(hi) : "l"(v));
}
__device__ __forceinline__ unsigned long long mul2(unsigned long long a,
                                                   unsigned long long b) {
    unsigned long long r;
    asm("mul.rn.f32x2 %0, %1, %2;" : "=l"(r) : "l"(a), "l"(b));
    return r;
}
__device__ __forceinline__ unsigned long long add2(unsigned long long a,
                                                   unsigned long long b) {
    unsigned long long r;
    asm("add.rn.f32x2 %0, %1, %2;" : "=l"(r) : "l"(a), "l"(b));
    return r;
}

#define PACK_BLOCKS 64   // 64*256 = 16384 pair threads
#define CLS_BLOCKS 128   // 128*256 = 32768 classify threads

// Fused pre-pass: blocks [0,PACK_BLOCKS) build the packed layout (R14
// verbatim); blocks [PACK_BLOCKS, PACK_BLOCKS+CLS_BLOCKS) classify queries by
// boundary proximity and build the LPT permutation (heavy = near >=2 faces ->
// front; these are the full-scan queries). Classification order is atomic-
// nondeterministic, but every query writes only its own output row, so the
// final output is deterministic. g_cnt is zeroed by ball_query_kernel for the
// next replay (it never reads g_cnt).
__global__ void pack_kernel(const float* __restrict__ xyz) {
    const int blk = blockIdx.x;
    if (blk < PACK_BLOCKS) {
        const int j = blk * 256 + threadIdx.x;       // pair index
        const int b = j / (NPTS / 2);
        const int s = j - b * (NPTS / 2);
        const int cp = s >> 5;
        const int l = s & 31;
        const int n0 = b * NPTS + cp * 64 + l;
        const int n1 = n0 + 32;

        const float x0 = xyz[n0 * 3 + 0], y0 = xyz[n0 * 3 + 1], z0 = xyz[n0 * 3 + 2];
        const float x1 = xyz[n1 * 3 + 0], y1 = xyz[n1 * 3 + 1], z1 = xyz[n1 * 3 + 2];
        const float w0 = __fadd_rn(__fadd_rn(__fmul_rn(x0, x0), __fmul_rn(y0, y0)),
                                   __fmul_rn(z0, z0));
        const float w1 = __fadd_rn(__fadd_rn(__fmul_rn(x1, x1), __fmul_rn(y1, y1)),
                                   __fmul_rn(z1, z1));
        const int base = (b * (NPTS / 64) + cp) * 64;
        g_pk[base + l]      = make_float4(x0, x1, y0, y1);
        g_pk[base + 32 + l] = make_float4(z0, z1, w0, w1);
    } else {
        const int qid = (blk - PACK_BLOCKS) * 256 + threadIdx.x;
        const float x = xyz[qid * 3 + 0];
        const float y = xyz[qid * 3 + 1];
        const float z = xyz[qid * 3 + 2];
        const int nf = (fminf(x, 1.0f - x) < 0.2f) +
                       (fminf(y, 1.0f - y) < 0.2f) +
                       (fminf(z, 1.0f - z) < 0.2f);
        const bool heavy = nf >= 2;   // near edge/corner -> near-full scan

        const int lane = threadIdx.x & 31;
        const unsigned mlt = (1u << lane) - 1u;
        const unsigned balH = __ballot_sync(0xffffffffu, heavy);
        const int nH = __popc(balH);
        unsigned baseH = 0, baseL = 0;
        if (lane == 0) {
            baseH = atomicAdd(&g_cnt[0], (unsigned)nH);
            baseL = atomicAdd(&g_cnt[1], (unsigned)(32 - nH));
        }
        baseH = __shfl_sync(0xffffffffu, baseH, 0);
        baseL = __shfl_sync(0xffffffffu, baseL, 0);
        int slot;
        if (heavy) slot = (int)(baseH + __popc(balH & mlt));
        else       slot = TOTALQ - 1 - (int)(baseL + __popc(~balH & mlt));
        g_perm[slot] = qid;
    }
}

// One warp per schedule slot; the slot's query id comes from the LPT
// permutation (heavy queries run in the first waves, light ones fill the
// tail). Scan body is the R14 kernel VERBATIM: 128 points/iter, depth-4
// prefetch, frozen f32x2 distance math, ballot-ordered deferred smem
// emission, select epilogue (copy + truncate + pad-with-first in one store).
__global__ void ball_query_kernel(const float* __restrict__ xyz,
                                  float* __restrict__ out) {
    __shared__ float scr[WARPS_PER_BLOCK][SCR_SLOTS];

    if (blockIdx.x == 0 && threadIdx.x == 0) {  // reset for next replay;
        g_cnt[0] = 0;                           // nothing here reads g_cnt
        g_cnt[1] = 0;
    }

    const int lane = threadIdx.x & 31;
    const int w = threadIdx.x >> 5;
    const int gw = blockIdx.x * WARPS_PER_BLOCK + w;
    const int qid = g_perm[gw];      // LPT-scheduled query
    const int b = qid >> 12;         // / NPTS

    const float4* __restrict__ p = g_pk + (size_t)b * NPTS;

    const float qx = xyz[qid * 3 + 0];
    const float qy = xyz[qid * 3 + 1];
    const float qz = xyz[qid * 3 + 2];
    const float qw = __fadd_rn(__fadd_rn(__fmul_rn(qx, qx), __fmul_rn(qy, qy)),
                               __fmul_rn(qz, qz));
    const unsigned long long qxp = pk2(qx, qx);
    const unsigned long long qyp = pk2(qy, qy);
    const unsigned long long qzp = pk2(qz, qz);
    const unsigned long long qwp = pk2(qw, qw);
    const unsigned long long M2  = pk2(-2.0f, -2.0f);

    const unsigned mlt = (1u << lane) - 1u;
    const float r2 = 0.04f;          // f32 promotion of 0.2*0.2
    int count = 0;

    float4 s0 = p[lane];
    float4 s1 = p[32 + lane];
    float4 s2 = p[64 + lane];
    float4 s3 = p[96 + lane];
    p += 128;

    float f0 = (float)lane;
    float f1 = (float)(lane + 32);
    float f2 = (float)(lane + 64);
    float f3 = (float)(lane + 96);

    for (int it = 0; it < NPTS / 128; ++it) {
        const float4 a0 = s0, b0 = s1, a1 = s2, b1 = s3;
        s0 = p[lane];                // final-iter overrun lands in the pad
        s1 = p[32 + lane];
        s2 = p[64 + lane];
        s3 = p[96 + lane];
        p += 128;

        const unsigned long long dotA =
            add2(add2(mul2(qxp, pk2(a0.x, a0.y)),
                      mul2(qyp, pk2(a0.z, a0.w))),
                 mul2(qzp, pk2(b0.x, b0.y)));
        const unsigned long long d2A =
            add2(add2(qwp, pk2(b0.z, b0.w)), mul2(dotA, M2));
        float d20, d21;
        upk2(d2A, d20, d21);

        const unsigned long long dotB =
            add2(add2(mul2(qxp, pk2(a1.x, a1.y)),
                      mul2(qyp, pk2(a1.z, a1.w))),
                 mul2(qzp, pk2(b1.x, b1.y)));
        const unsigned long long d2B =
            add2(add2(qwp, pk2(b1.z, b1.w)), mul2(dotB, M2));
        float d22, d23;
        upk2(d2B, d22, d23);

        const bool h0 = d20 < r2;
        const bool h1 = d21 < r2;
        const bool h2 = d22 < r2;
        const bool h3 = d23 < r2;
        const unsigned bal0 = __ballot_sync(0xffffffffu, h0);
        const unsigned bal1 = __ballot_sync(0xffffffffu, h1);
        const unsigned bal2 = __ballot_sync(0xffffffffu, h2);
        const unsigned bal3 = __ballot_sync(0xffffffffu, h3);

        if (h0) scr[w][count + __popc(bal0 & mlt)] = f0;
        int cn = count + __popc(bal0);
        if (h1) scr[w][cn + __popc(bal1 & mlt)] = f1;
        cn += __popc(bal1);
        if (h2) scr[w][cn + __popc(bal2 & mlt)] = f2;
        cn += __popc(bal2);
        if (h3) scr[w][cn + __popc(bal3 & mlt)] = f3;
        count = cn + __popc(bal3);

        f0 += 128.0f;
        f1 += 128.0f;
        f2 += 128.0f;
        f3 += 128.0f;

        if (count >= NSAMPLE) break;  // count is warp-uniform
    }

    __syncwarp();                     // order scratch stores within the warp
    const int sel = (lane < count) ? lane : 0;  // scr[0] == smallest hit
    out[(size_t)qid * NSAMPLE + lane] = scr[w][sel];
}

extern "C" void kernel_launch(void* const* d_in, const int* in_sizes, int n_in,
                              void* d_out, int out_size) {
    const float* xyz = (const float*)d_in[0];  // 'xyz' (B, N, 3) float32
    // d_in[1] ('xyz_new') is unused by the reference (it queries xyz vs xyz).
    float* out = (float*)d_out;

    pack_kernel<<<PACK_BLOCKS + CLS_BLOCKS, 256>>>(xyz);

    const int blocks = TOTALQ / WARPS_PER_BLOCK;  // 16384
    ball_query_kernel<<<blocks, BLOCK_THREADS>>>(xyz, out);
}